// round 15
// baseline (speedup 1.0000x reference)
#include <cuda_runtime.h>
#include <cstdint>

#define BDIM 8
#define CDIM 256
#define SDIM 16384
#define BK 32
#define NSLAB 32
#define KD 21              // diag split-K chunks (2-chain tiles)
#define KO 32              // off-diag split-K chunks (3-chain tiles)
#define G1_CTAS 74         // per-batch gemm1 CTAs
#define HB (BDIM / 2)      // 4 batches per group

// Scratch (static device memory — allowed; no runtime allocation).
__device__ float g_Ep[NSLAB][BDIM * CDIM * CDIM];  // split-K partials of E
__device__ float g_W[BDIM * CDIM * CDIM];          // softmax weights

__device__ __forceinline__ float tr32(float v) {
    return __uint_as_float(__float_as_uint(v) & 0xFFFFE000u);
}
__device__ __forceinline__ void split_mask(float v, uint32_t& hi, uint32_t& lo) {
    hi = __float_as_uint(v);
    lo = __float_as_uint(v - tr32(v));
}
__device__ __forceinline__ uint32_t tf32rn(float x) {
    uint32_t u;
    asm("cvt.rna.tf32.f32 %0, %1;" : "=r"(u) : "f"(x));
    return u;
}

__device__ __forceinline__ void mma_tf32(float* d, const uint32_t* a, const uint32_t* b) {
    asm volatile(
        "mma.sync.aligned.m16n8k8.row.col.f32.tf32.tf32.f32 "
        "{%0,%1,%2,%3}, {%4,%5,%6,%7}, {%8,%9}, {%0,%1,%2,%3};\n"
        : "+f"(d[0]), "+f"(d[1]), "+f"(d[2]), "+f"(d[3])
        : "r"(a[0]), "r"(a[1]), "r"(a[2]), "r"(a[3]), "r"(b[0]), "r"(b[1]));
}

__device__ __forceinline__ void mma3(float* d, const uint32_t* ah, const uint32_t* al,
                                     const uint32_t* bh, const uint32_t* bl) {
    mma_tf32(d, ah, bh);
    mma_tf32(d, al, bh);
    mma_tf32(d, ah, bl);
}

__device__ __forceinline__ void cp16(void* s, const void* g) {
    uint32_t sa = (uint32_t)__cvta_generic_to_shared(s);
    asm volatile("cp.async.cg.shared.global [%0], [%1], 16;" :: "r"(sa), "l"(g));
}
#define CP_COMMIT() asm volatile("cp.async.commit_group;")
template <int N> __device__ __forceinline__ void cp_wait() {
    asm volatile("cp.async.wait_group %0;" :: "n"(N));
}

// ---------------------------------------------------------------------------
// GEMM1 body: one 128x128 tile of E_partial for (idx in 0..73, batch b).
// 256 threads. Diag tiles: 2 chains + D1+D1^T transpose epilogue.
// Off-diag: 3 chains + mirror store.
// ---------------------------------------------------------------------------
__device__ __forceinline__ void gemm1_body(const float* __restrict__ x,
                                           int idx, int b, float* smem) {
    const float* __restrict__ V = x + (size_t)b * CDIM * SDIM;

    int ks, tm, tn, blk0, nblk;
    bool diag;
    if (idx < 2 * KD) {
        diag = true;
        const int t = (idx < KD) ? 0 : 1;
        ks = idx - t * KD;
        tm = tn = t * 128;
        blk0 = ks * 24 + (ks < 8 ? ks : 8);
        nblk = 24 + (ks < 8 ? 1 : 0);
    } else {
        diag = false;
        ks = idx - 2 * KD;
        tm = 0; tn = 128;
        blk0 = ks * 16;
        nblk = 16;
    }
    const int kb0 = blk0 * BK;
    const int kb1 = kb0 + nblk * BK;

    const int TILE = 128 * 36;
    const int tid  = threadIdx.x;
    const int lane = tid & 31;
    const int wid  = tid >> 5;
    const int gid  = lane >> 2;
    const int tig  = lane & 3;
    const int warpM = wid >> 2;
    const int warpN = wid & 3;

    float acc[4][4][4];
    #pragma unroll
    for (int i = 0; i < 4; i++)
        #pragma unroll
        for (int j = 0; j < 4; j++)
            #pragma unroll
            for (int k = 0; k < 4; k++) acc[i][j][k] = 0.f;

    const int ldRow = tid >> 3;
    const int ldCol = (tid & 7) * 4;

    auto issue = [&](int buf, int kb) {
        float* A = smem + buf * 2 * TILE;
        float* B = A + TILE;
        #pragma unroll
        for (int p = 0; p < 4; p++) {
            const int row = p * 32 + ldRow;
            cp16(A + row * 36 + ldCol, V + (size_t)(tm + row) * SDIM + kb + ldCol);
            if (!diag)
                cp16(B + row * 36 + ldCol, V + (size_t)(tn + row) * SDIM + kb + ldCol);
        }
        CP_COMMIT();
    };

    issue(0, kb0);
    int buf = 0;

    for (int kb = kb0; kb < kb1; kb += BK) {
        const bool more = (kb + BK < kb1);
        if (more) issue(buf ^ 1, kb + BK);
        if (more) cp_wait<1>(); else cp_wait<0>();
        __syncthreads();

        float* A = smem + buf * 2 * TILE;

        if (diag) {
            #pragma unroll
            for (int kk = 0; kk < BK; kk += 8) {
                uint32_t ar[4][4], bh2[4][2], bl[4][2];
                #pragma unroll
                for (int mr = 0; mr < 4; mr++) {
                    const int r0 = warpM * 64 + mr * 16;
                    ar[mr][0] = __float_as_uint(A[(r0 + gid    ) * 36 + kk + tig    ]);
                    ar[mr][1] = __float_as_uint(A[(r0 + 8 + gid) * 36 + kk + tig    ]);
                    ar[mr][2] = __float_as_uint(A[(r0 + gid    ) * 36 + kk + tig + 4]);
                    ar[mr][3] = __float_as_uint(A[(r0 + 8 + gid) * 36 + kk + tig + 4]);
                }
                #pragma unroll
                for (int nc = 0; nc < 4; nc++) {
                    const int n0 = warpN * 32 + nc * 8;
                    const float v0 = A[(n0 + gid) * 36 + kk + tig    ];
                    const float v1 = A[(n0 + gid) * 36 + kk + tig + 4];
                    bh2[nc][0] = __float_as_uint(0.5f * v0);
                    bh2[nc][1] = __float_as_uint(0.5f * v1);
                    bl[nc][0]  = __float_as_uint(v0 - tr32(v0));
                    bl[nc][1]  = __float_as_uint(v1 - tr32(v1));
                }
                #pragma unroll
                for (int mr = 0; mr < 4; mr++)
                    #pragma unroll
                    for (int nc = 0; nc < 4; nc++) {
                        mma_tf32(acc[mr][nc], ar[mr], bh2[nc]);
                        mma_tf32(acc[mr][nc], ar[mr], bl[nc]);
                    }
            }
        } else {
            float* B = A + TILE;
            #pragma unroll
            for (int kk = 0; kk < BK; kk += 8) {
                uint32_t ah[4][4], al[4][4], bh[4][2], bl[4][2];
                #pragma unroll
                for (int mr = 0; mr < 4; mr++) {
                    const int r0 = warpM * 64 + mr * 16;
                    split_mask(A[(r0 + gid    ) * 36 + kk + tig    ], ah[mr][0], al[mr][0]);
                    split_mask(A[(r0 + 8 + gid) * 36 + kk + tig    ], ah[mr][1], al[mr][1]);
                    split_mask(A[(r0 + gid    ) * 36 + kk + tig + 4], ah[mr][2], al[mr][2]);
                    split_mask(A[(r0 + 8 + gid) * 36 + kk + tig + 4], ah[mr][3], al[mr][3]);
                }
                #pragma unroll
                for (int nc = 0; nc < 4; nc++) {
                    const int n0 = warpN * 32 + nc * 8;
                    split_mask(B[(n0 + gid) * 36 + kk + tig    ], bh[nc][0], bl[nc][0]);
                    split_mask(B[(n0 + gid) * 36 + kk + tig + 4], bh[nc][1], bl[nc][1]);
                }
                #pragma unroll
                for (int mr = 0; mr < 4; mr++)
                    #pragma unroll
                    for (int nc = 0; nc < 4; nc++)
                        mma3(acc[mr][nc], ah[mr], al[mr], bh[nc], bl[nc]);
            }
        }
        __syncthreads();
        buf ^= 1;
    }

    float* Ep = &g_Ep[ks][(size_t)b * CDIM * CDIM];

    if (diag) {
        float* Et = smem;
        #pragma unroll
        for (int mr = 0; mr < 4; mr++) {
            const int r = warpM * 64 + mr * 16 + gid;
            #pragma unroll
            for (int nc = 0; nc < 4; nc++) {
                const int c = warpN * 32 + nc * 8 + tig * 2;
                Et[r * 129 + c]           = acc[mr][nc][0];
                Et[r * 129 + c + 1]       = acc[mr][nc][1];
                Et[(r + 8) * 129 + c]     = acc[mr][nc][2];
                Et[(r + 8) * 129 + c + 1] = acc[mr][nc][3];
            }
        }
        __syncthreads();
        #pragma unroll
        for (int mr = 0; mr < 4; mr++) {
            const int r = warpM * 64 + mr * 16 + gid;
            #pragma unroll
            for (int nc = 0; nc < 4; nc++) {
                const int c = warpN * 32 + nc * 8 + tig * 2;
                const float e0 = acc[mr][nc][0] + Et[c * 129 + r];
                const float e1 = acc[mr][nc][1] + Et[(c + 1) * 129 + r];
                const float e2 = acc[mr][nc][2] + Et[c * 129 + r + 8];
                const float e3 = acc[mr][nc][3] + Et[(c + 1) * 129 + r + 8];
                *(float2*)&Ep[(size_t)(tm + r) * CDIM + tm + c]     = make_float2(e0, e1);
                *(float2*)&Ep[(size_t)(tm + r + 8) * CDIM + tm + c] = make_float2(e2, e3);
            }
        }
    } else {
        #pragma unroll
        for (int mr = 0; mr < 4; mr++) {
            const int r = tm + warpM * 64 + mr * 16 + gid;
            #pragma unroll
            for (int nc = 0; nc < 4; nc++) {
                const int c = tn + warpN * 32 + nc * 8 + tig * 2;
                *(float2*)&Ep[(size_t)r * CDIM + c]       = make_float2(acc[mr][nc][0], acc[mr][nc][1]);
                *(float2*)&Ep[(size_t)(r + 8) * CDIM + c] = make_float2(acc[mr][nc][2], acc[mr][nc][3]);
                Ep[(size_t)c * CDIM + r]           = acc[mr][nc][0];
                Ep[(size_t)(c + 1) * CDIM + r]     = acc[mr][nc][1];
                Ep[(size_t)c * CDIM + r + 8]       = acc[mr][nc][2];
                Ep[(size_t)(c + 1) * CDIM + r + 8] = acc[mr][nc][3];
            }
        }
    }
}

// ---------------------------------------------------------------------------
// GEMM2 body: one 128x128 out tile (mTile selects M half). 256 threads.
// Single-chain tf32, rna-rounded operands. 2-stage cp.async.
// ---------------------------------------------------------------------------
__device__ __forceinline__ void gemm2_body(const float* __restrict__ x,
                                           const float* __restrict__ alpha,
                                           float* __restrict__ out,
                                           int sTile, int mTile, int b, float* smem) {
    const int s0 = sTile * 128;
    const int m0 = mTile * 128;
    const float* __restrict__ V  = x + (size_t)b * CDIM * SDIM;
    const float* __restrict__ Wm = g_W + (size_t)b * CDIM * CDIM;

    const int ATILE = 128 * 36;
    const int BTILE = 32 * 136;
    const int STAGE = ATILE + BTILE;

    const int tid  = threadIdx.x;
    const int lane = tid & 31;
    const int wid  = tid >> 5;
    const int gid  = lane >> 2;
    const int tig  = lane & 3;
    const int warpM = wid >> 2;
    const int warpN = wid & 3;

    float acc[4][4][4];
    #pragma unroll
    for (int i = 0; i < 4; i++)
        #pragma unroll
        for (int j = 0; j < 4; j++)
            #pragma unroll
            for (int k = 0; k < 4; k++) acc[i][j][k] = 0.f;

    const int aRow = tid >> 3;
    const int aCol = (tid & 7) * 4;
    const int bRowBase = tid >> 5;
    const int bCol = (tid & 31) * 4;

    auto issue = [&](int buf, int kb) {
        float* A = smem + buf * STAGE;
        float* B = A + ATILE;
        #pragma unroll
        for (int p = 0; p < 4; p++) {
            const int row = p * 32 + aRow;
            cp16(A + row * 36 + aCol, Wm + (size_t)(m0 + row) * CDIM + kb + aCol);
        }
        #pragma unroll
        for (int p = 0; p < 4; p++) {
            const int kr = p * 8 + bRowBase;
            cp16(B + kr * 136 + bCol, V + (size_t)(kb + kr) * SDIM + s0 + bCol);
        }
        CP_COMMIT();
    };

    issue(0, 0);
    int buf = 0;

    for (int kb = 0; kb < CDIM; kb += BK) {
        const bool more = (kb + BK < CDIM);
        if (more) issue(buf ^ 1, kb + BK);
        if (more) cp_wait<1>(); else cp_wait<0>();
        __syncthreads();

        float* A = smem + buf * STAGE;
        float* B = A + ATILE;

        #pragma unroll
        for (int kk = 0; kk < BK; kk += 8) {
            uint32_t ah[4][4], bh[4][2];
            #pragma unroll
            for (int mr = 0; mr < 4; mr++) {
                const int r0 = warpM * 64 + mr * 16;
                ah[mr][0] = tf32rn(A[(r0 + gid    ) * 36 + kk + tig    ]);
                ah[mr][1] = tf32rn(A[(r0 + 8 + gid) * 36 + kk + tig    ]);
                ah[mr][2] = tf32rn(A[(r0 + gid    ) * 36 + kk + tig + 4]);
                ah[mr][3] = tf32rn(A[(r0 + 8 + gid) * 36 + kk + tig + 4]);
            }
            #pragma unroll
            for (int nc = 0; nc < 4; nc++) {
                const int n0 = warpN * 32 + nc * 8;
                bh[nc][0] = tf32rn(B[(kk + tig    ) * 136 + n0 + gid]);
                bh[nc][1] = tf32rn(B[(kk + tig + 4) * 136 + n0 + gid]);
            }
            #pragma unroll
            for (int mr = 0; mr < 4; mr++)
                #pragma unroll
                for (int nc = 0; nc < 4; nc++)
                    mma_tf32(acc[mr][nc], ah[mr], bh[nc]);
        }
        __syncthreads();
        buf ^= 1;
    }

    const float av = *alpha;
    float* outB = out + (size_t)b * CDIM * SDIM;
    #pragma unroll
    for (int mr = 0; mr < 4; mr++) {
        const int r = m0 + warpM * 64 + mr * 16 + gid;
        #pragma unroll
        for (int nc = 0; nc < 4; nc++) {
            const int s = s0 + warpN * 32 + nc * 8 + tig * 2;
            const size_t i0 = (size_t)r * SDIM + s;
            const size_t i1 = i0 + (size_t)8 * SDIM;
            const float2 x0 = *(const float2*)(V + i0);
            const float2 x1 = *(const float2*)(V + i1);
            *(float2*)(outB + i0) = make_float2(fmaf(av, acc[mr][nc][0], x0.x),
                                                fmaf(av, acc[mr][nc][1], x0.y));
            *(float2*)(outB + i1) = make_float2(fmaf(av, acc[mr][nc][2], x1.x),
                                                fmaf(av, acc[mr][nc][3], x1.y));
        }
    }
}

// ---------------------------------------------------------------------------
// Standalone GEMM1 (group A warm-up phase).
// ---------------------------------------------------------------------------
__global__ __launch_bounds__(256, 2) void gemm1_kernel(const float* __restrict__ x, int b0) {
    extern __shared__ float smem[];
    gemm1_body(x, blockIdx.x, b0 + blockIdx.y, smem);
}

// ---------------------------------------------------------------------------
// Fused role kernel: Bresenham-interleaved mix of gemm2 CTAs (role A,
// aTotal of them, batches aB0..) and gemm1 CTAs (role B, bTotal, batches bB0..).
// Same resource shape for both roles -> co-resident on every SM.
// ---------------------------------------------------------------------------
__global__ __launch_bounds__(256, 2) void fused_kernel(const float* __restrict__ x,
                                                       const float* __restrict__ alpha,
                                                       float* __restrict__ out,
                                                       int aTotal, int aB0,
                                                       int bTotal, int bB0) {
    extern __shared__ float smem[];
    const int idx = blockIdx.x;
    const long total = aTotal + bTotal;
    const int aBefore = (int)((long)idx * aTotal / total);
    const int aAfter  = (int)((long)(idx + 1) * aTotal / total);
    if (aAfter > aBefore) {
        const int aIdx = aBefore;             // 0..aTotal-1
        const int sTile = aIdx & 127;
        const int mTile = (aIdx >> 7) & 1;
        const int b     = aB0 + (aIdx >> 8);
        gemm2_body(x, alpha, out, sTile, mTile, b, smem);
    } else {
        const int bIdx = idx - aBefore;       // 0..bTotal-1
        gemm1_body(x, bIdx % G1_CTAS, bB0 + bIdx / G1_CTAS, smem);
    }
}

// ---------------------------------------------------------------------------
// Softmax: reduce split-K partials (21 slabs diag quadrants, 32 off-diag),
// then w[row,:] = softmax(-E[row,:]).  row0 = group offset.
// ---------------------------------------------------------------------------
__global__ __launch_bounds__(256) void softmax_kernel(int row0) {
    const int row = row0 + blockIdx.x;
    const int r   = row & (CDIM - 1);
    const int tid = threadIdx.x;
    const int lane = tid & 31;
    const int wid  = tid >> 5;

    const bool diagq = ((r < 128) == (tid < 128));
    const size_t off = (size_t)row * CDIM + tid;

    float e = 0.f;
    #pragma unroll
    for (int k = 0; k < KD; k++) e += g_Ep[k][off];
    if (!diagq) {
        #pragma unroll
        for (int k = KD; k < KO; k++) e += g_Ep[k][off];
    }

    __shared__ float red[8];

    float m = e;
    #pragma unroll
    for (int o = 16; o > 0; o >>= 1) m = fminf(m, __shfl_xor_sync(0xffffffffu, m, o));
    if (lane == 0) red[wid] = m;
    __syncthreads();
    float mn = red[0];
    #pragma unroll
    for (int i = 1; i < 8; i++) mn = fminf(mn, red[i]);
    __syncthreads();

    const float ex = expf(mn - e);

    float s = ex;
    #pragma unroll
    for (int o = 16; o > 0; o >>= 1) s += __shfl_xor_sync(0xffffffffu, s, o);
    if (lane == 0) red[wid] = s;
    __syncthreads();
    float st = red[0];
    #pragma unroll
    for (int i = 1; i < 8; i++) st += red[i];

    g_W[off] = ex / st;
}

extern "C" void kernel_launch(void* const* d_in, const int* in_sizes, int n_in,
                              void* d_out, int out_size) {
    const float* x     = (const float*)d_in[0];
    const float* alpha = (const float*)d_in[1];
    float* out = (float*)d_out;

    const int smemF = 4 * 128 * 36 * 4;   // 73728 B (covers both roles)
    cudaFuncSetAttribute(gemm1_kernel, cudaFuncAttributeMaxDynamicSharedMemorySize, smemF);
    cudaFuncSetAttribute(fused_kernel, cudaFuncAttributeMaxDynamicSharedMemorySize, smemF);

    const int G2A = 128 * 2 * HB;         // 1024 gemm2 CTAs per group
    const int G1B = G1_CTAS * HB;         // 296 gemm1 CTAs per group

    // Phase 1: gemm1 group A (batches 0..3)
    gemm1_kernel<<<dim3(G1_CTAS, HB), 256, smemF>>>(x, 0);
    // Phase 2: softmax group A
    softmax_kernel<<<HB * CDIM, 256>>>(0);
    // Phase 3: gemm2(A)  ∥  gemm1(B)  — co-resident role mix
    fused_kernel<<<G2A + G1B, 256, smemF>>>(x, alpha, out, G2A, 0, G1B, HB);
    // Phase 4: softmax group B
    softmax_kernel<<<HB * CDIM, 256>>>(HB * CDIM);
    // Phase 5: gemm2 group B (all role A)
    fused_kernel<<<G2A, 256, smemF>>>(x, alpha, out, G2A, HB, 0, 0);
}

// round 17
// speedup vs baseline: 1.1561x; 1.1561x over previous
#include <cuda_runtime.h>
#include <cstdint>

#define BDIM 8
#define CDIM 256
#define SDIM 16384
#define BK 32
#define NSLAB 32
#define KD 21              // diag split-K chunks (2-chain tiles)
#define KO 32              // off-diag split-K chunks (3-chain tiles)
#define G1_CTAS 74         // per-batch gemm1 CTAs
#define HB (BDIM / 2)      // 4 batches per group

// Scratch (static device memory — allowed; no runtime allocation).
__device__ float g_Ep[NSLAB][BDIM * CDIM * CDIM];  // split-K partials of E
__device__ float g_W[BDIM * CDIM * CDIM];          // softmax weights

__device__ __forceinline__ float tr32(float v) {
    return __uint_as_float(__float_as_uint(v) & 0xFFFFE000u);
}
__device__ __forceinline__ void split_mask(float v, uint32_t& hi, uint32_t& lo) {
    hi = __float_as_uint(v);
    lo = __float_as_uint(v - tr32(v));
}
__device__ __forceinline__ uint32_t tf32rn(float x) {
    uint32_t u;
    asm("cvt.rna.tf32.f32 %0, %1;" : "=r"(u) : "f"(x));
    return u;
}

__device__ __forceinline__ void mma_tf32(float* d, const uint32_t* a, const uint32_t* b) {
    asm volatile(
        "mma.sync.aligned.m16n8k8.row.col.f32.tf32.tf32.f32 "
        "{%0,%1,%2,%3}, {%4,%5,%6,%7}, {%8,%9}, {%0,%1,%2,%3};\n"
        : "+f"(d[0]), "+f"(d[1]), "+f"(d[2]), "+f"(d[3])
        : "r"(a[0]), "r"(a[1]), "r"(a[2]), "r"(a[3]), "r"(b[0]), "r"(b[1]));
}

__device__ __forceinline__ void mma3(float* d, const uint32_t* ah, const uint32_t* al,
                                     const uint32_t* bh, const uint32_t* bl) {
    mma_tf32(d, ah, bh);
    mma_tf32(d, al, bh);
    mma_tf32(d, ah, bl);
}

__device__ __forceinline__ void cp16(void* s, const void* g) {
    uint32_t sa = (uint32_t)__cvta_generic_to_shared(s);
    asm volatile("cp.async.cg.shared.global [%0], [%1], 16;" :: "r"(sa), "l"(g));
}
#define CP_COMMIT() asm volatile("cp.async.commit_group;")
template <int N> __device__ __forceinline__ void cp_wait() {
    asm volatile("cp.async.wait_group %0;" :: "n"(N));
}

// ---------------------------------------------------------------------------
// GEMM1: E_partial = V_chunk * V_chunk^T with per-tile-type balanced split-K.
// grid.x = 74 per batch. b0 = batch offset of this group. (Unchanged, R12-best.)
// ---------------------------------------------------------------------------
__global__ __launch_bounds__(256, 2) void gemm1_kernel(const float* __restrict__ x, int b0) {
    const int idx = blockIdx.x;            // 0..73
    const int b   = b0 + blockIdx.y;
    const float* __restrict__ V = x + (size_t)b * CDIM * SDIM;

    int ks, tm, tn, blk0, nblk;
    bool diag;
    if (idx < 2 * KD) {
        diag = true;
        const int t = (idx < KD) ? 0 : 1;
        ks = idx - t * KD;
        tm = tn = t * 128;
        blk0 = ks * 24 + (ks < 8 ? ks : 8);
        nblk = 24 + (ks < 8 ? 1 : 0);
    } else {
        diag = false;
        ks = idx - 2 * KD;
        tm = 0; tn = 128;
        blk0 = ks * 16;
        nblk = 16;
    }
    const int kb0 = blk0 * BK;
    const int kb1 = kb0 + nblk * BK;

    extern __shared__ float smem[];
    const int TILE = 128 * 36;

    const int tid  = threadIdx.x;
    const int lane = tid & 31;
    const int wid  = tid >> 5;
    const int gid  = lane >> 2;
    const int tig  = lane & 3;
    const int warpM = wid >> 2;
    const int warpN = wid & 3;

    float acc[4][4][4];
    #pragma unroll
    for (int i = 0; i < 4; i++)
        #pragma unroll
        for (int j = 0; j < 4; j++)
            #pragma unroll
            for (int k = 0; k < 4; k++) acc[i][j][k] = 0.f;

    const int ldRow = tid >> 3;
    const int ldCol = (tid & 7) * 4;

    auto issue = [&](int buf, int kb) {
        float* A = smem + buf * 2 * TILE;
        float* B = A + TILE;
        #pragma unroll
        for (int p = 0; p < 4; p++) {
            const int row = p * 32 + ldRow;
            cp16(A + row * 36 + ldCol, V + (size_t)(tm + row) * SDIM + kb + ldCol);
            if (!diag)
                cp16(B + row * 36 + ldCol, V + (size_t)(tn + row) * SDIM + kb + ldCol);
        }
        CP_COMMIT();
    };

    issue(0, kb0);
    int buf = 0;

    for (int kb = kb0; kb < kb1; kb += BK) {
        const bool more = (kb + BK < kb1);
        if (more) issue(buf ^ 1, kb + BK);
        if (more) cp_wait<1>(); else cp_wait<0>();
        __syncthreads();

        float* A = smem + buf * 2 * TILE;

        if (diag) {
            #pragma unroll
            for (int kk = 0; kk < BK; kk += 8) {
                uint32_t ar[4][4], bh2[4][2], bl[4][2];
                #pragma unroll
                for (int mr = 0; mr < 4; mr++) {
                    const int r0 = warpM * 64 + mr * 16;
                    ar[mr][0] = __float_as_uint(A[(r0 + gid    ) * 36 + kk + tig    ]);
                    ar[mr][1] = __float_as_uint(A[(r0 + 8 + gid) * 36 + kk + tig    ]);
                    ar[mr][2] = __float_as_uint(A[(r0 + gid    ) * 36 + kk + tig + 4]);
                    ar[mr][3] = __float_as_uint(A[(r0 + 8 + gid) * 36 + kk + tig + 4]);
                }
                #pragma unroll
                for (int nc = 0; nc < 4; nc++) {
                    const int n0 = warpN * 32 + nc * 8;
                    const float v0 = A[(n0 + gid) * 36 + kk + tig    ];
                    const float v1 = A[(n0 + gid) * 36 + kk + tig + 4];
                    bh2[nc][0] = __float_as_uint(0.5f * v0);
                    bh2[nc][1] = __float_as_uint(0.5f * v1);
                    bl[nc][0]  = __float_as_uint(v0 - tr32(v0));
                    bl[nc][1]  = __float_as_uint(v1 - tr32(v1));
                }
                #pragma unroll
                for (int mr = 0; mr < 4; mr++)
                    #pragma unroll
                    for (int nc = 0; nc < 4; nc++) {
                        mma_tf32(acc[mr][nc], ar[mr], bh2[nc]);
                        mma_tf32(acc[mr][nc], ar[mr], bl[nc]);
                    }
            }
        } else {
            float* B = A + TILE;
            #pragma unroll
            for (int kk = 0; kk < BK; kk += 8) {
                uint32_t ah[4][4], al[4][4], bh[4][2], bl[4][2];
                #pragma unroll
                for (int mr = 0; mr < 4; mr++) {
                    const int r0 = warpM * 64 + mr * 16;
                    split_mask(A[(r0 + gid    ) * 36 + kk + tig    ], ah[mr][0], al[mr][0]);
                    split_mask(A[(r0 + 8 + gid) * 36 + kk + tig    ], ah[mr][1], al[mr][1]);
                    split_mask(A[(r0 + gid    ) * 36 + kk + tig + 4], ah[mr][2], al[mr][2]);
                    split_mask(A[(r0 + 8 + gid) * 36 + kk + tig + 4], ah[mr][3], al[mr][3]);
                }
                #pragma unroll
                for (int nc = 0; nc < 4; nc++) {
                    const int n0 = warpN * 32 + nc * 8;
                    split_mask(B[(n0 + gid) * 36 + kk + tig    ], bh[nc][0], bl[nc][0]);
                    split_mask(B[(n0 + gid) * 36 + kk + tig + 4], bh[nc][1], bl[nc][1]);
                }
                #pragma unroll
                for (int mr = 0; mr < 4; mr++)
                    #pragma unroll
                    for (int nc = 0; nc < 4; nc++)
                        mma3(acc[mr][nc], ah[mr], al[mr], bh[nc], bl[nc]);
            }
        }
        __syncthreads();
        buf ^= 1;
    }

    float* Ep = &g_Ep[ks][(size_t)b * CDIM * CDIM];

    if (diag) {
        float* Et = smem;
        #pragma unroll
        for (int mr = 0; mr < 4; mr++) {
            const int r = warpM * 64 + mr * 16 + gid;
            #pragma unroll
            for (int nc = 0; nc < 4; nc++) {
                const int c = warpN * 32 + nc * 8 + tig * 2;
                Et[r * 129 + c]           = acc[mr][nc][0];
                Et[r * 129 + c + 1]       = acc[mr][nc][1];
                Et[(r + 8) * 129 + c]     = acc[mr][nc][2];
                Et[(r + 8) * 129 + c + 1] = acc[mr][nc][3];
            }
        }
        __syncthreads();
        #pragma unroll
        for (int mr = 0; mr < 4; mr++) {
            const int r = warpM * 64 + mr * 16 + gid;
            #pragma unroll
            for (int nc = 0; nc < 4; nc++) {
                const int c = warpN * 32 + nc * 8 + tig * 2;
                const float e0 = acc[mr][nc][0] + Et[c * 129 + r];
                const float e1 = acc[mr][nc][1] + Et[(c + 1) * 129 + r];
                const float e2 = acc[mr][nc][2] + Et[c * 129 + r + 8];
                const float e3 = acc[mr][nc][3] + Et[(c + 1) * 129 + r + 8];
                *(float2*)&Ep[(size_t)(tm + r) * CDIM + tm + c]     = make_float2(e0, e1);
                *(float2*)&Ep[(size_t)(tm + r + 8) * CDIM + tm + c] = make_float2(e2, e3);
            }
        }
    } else {
        #pragma unroll
        for (int mr = 0; mr < 4; mr++) {
            const int r = tm + warpM * 64 + mr * 16 + gid;
            #pragma unroll
            for (int nc = 0; nc < 4; nc++) {
                const int c = tn + warpN * 32 + nc * 8 + tig * 2;
                *(float2*)&Ep[(size_t)r * CDIM + c]       = make_float2(acc[mr][nc][0], acc[mr][nc][1]);
                *(float2*)&Ep[(size_t)(r + 8) * CDIM + c] = make_float2(acc[mr][nc][2], acc[mr][nc][3]);
                Ep[(size_t)c * CDIM + r]           = acc[mr][nc][0];
                Ep[(size_t)(c + 1) * CDIM + r]     = acc[mr][nc][1];
                Ep[(size_t)c * CDIM + r + 8]       = acc[mr][nc][2];
                Ep[(size_t)(c + 1) * CDIM + r + 8] = acc[mr][nc][3];
            }
        }
    }
}

// ---------------------------------------------------------------------------
// Softmax: reduce split-K partials (21 slabs diag quadrants, 32 off-diag),
// then w[row,:] = softmax(-E[row,:]).  row0 = group offset. (Unchanged.)
// ---------------------------------------------------------------------------
__global__ __launch_bounds__(256) void softmax_kernel(int row0) {
    const int row = row0 + blockIdx.x;
    const int r   = row & (CDIM - 1);
    const int tid = threadIdx.x;
    const int lane = tid & 31;
    const int wid  = tid >> 5;

    const bool diagq = ((r < 128) == (tid < 128));
    const size_t off = (size_t)row * CDIM + tid;

    float e = 0.f;
    #pragma unroll
    for (int k = 0; k < KD; k++) e += g_Ep[k][off];
    if (!diagq) {
        #pragma unroll
        for (int k = KD; k < KO; k++) e += g_Ep[k][off];
    }

    __shared__ float red[8];

    float m = e;
    #pragma unroll
    for (int o = 16; o > 0; o >>= 1) m = fminf(m, __shfl_xor_sync(0xffffffffu, m, o));
    if (lane == 0) red[wid] = m;
    __syncthreads();
    float mn = red[0];
    #pragma unroll
    for (int i = 1; i < 8; i++) mn = fminf(mn, red[i]);
    __syncthreads();

    const float ex = expf(mn - e);

    float s = ex;
    #pragma unroll
    for (int o = 16; o > 0; o >>= 1) s += __shfl_xor_sync(0xffffffffu, s, o);
    if (lane == 0) red[wid] = s;
    __syncthreads();
    float st = red[0];
    #pragma unroll
    for (int i = 1; i < 8; i++) st += red[i];

    g_W[off] = ex / st;
}

// ---------------------------------------------------------------------------
// GEMM2: out = alpha * (W @ V) + x.  256x64 tile per CTA, 256 threads
// (8 warps, 4x2; 64x32 per warp). 92 KB smem, ~125 regs -> 2 CTAs/SM, so one
// CTA's STG epilogue overlaps the co-resident CTA's tensor mainloop.
// V column slab still read once chip-wide. Single-chain rna tf32.
// ---------------------------------------------------------------------------
__global__ __launch_bounds__(256, 2) void gemm2_kernel(const float* __restrict__ x,
                                                       const float* __restrict__ alpha,
                                                       float* __restrict__ out, int b0) {
    const int sTile = blockIdx.x;   // 0..255
    const int b     = b0 + blockIdx.y;
    const int s0 = sTile * 64;
    const float* __restrict__ V  = x + (size_t)b * CDIM * SDIM;
    const float* __restrict__ Wm = g_W + (size_t)b * CDIM * CDIM;

    extern __shared__ float smem[];
    const int ATILE = 256 * 36;   // W tile [m=256][k=32]
    const int BTILE = 32 * 72;    // V tile [k=32][n=64] (pad 72)
    const int STAGE = ATILE + BTILE;

    const int tid  = threadIdx.x;
    const int lane = tid & 31;
    const int wid  = tid >> 5;       // 0..7
    const int gid  = lane >> 2;
    const int tig  = lane & 3;
    const int warpM = wid >> 1;      // 0..3 -> 64 rows each
    const int warpN = wid & 1;       // 0..1 -> 32 cols each

    float acc[4][4][4];
    #pragma unroll
    for (int i = 0; i < 4; i++)
        #pragma unroll
        for (int j = 0; j < 4; j++)
            #pragma unroll
            for (int k = 0; k < 4; k++) acc[i][j][k] = 0.f;

    const int aRow = tid >> 3;           // 0..31
    const int aCol = (tid & 7) * 4;      // 0..28

    auto issue = [&](int buf, int kb) {
        float* A = smem + buf * STAGE;
        float* B = A + ATILE;
        #pragma unroll
        for (int p = 0; p < 8; p++) {
            const int row = p * 32 + aRow;       // 0..255
            cp16(A + row * 36 + aCol, Wm + (size_t)row * CDIM + kb + aCol);
        }
        #pragma unroll
        for (int q = 0; q < 2; q++) {
            const int c = tid + 256 * q;         // 0..511 chunks of 16B
            const int k = c >> 4, sc = c & 15;   // 16 chunks per 64-wide row
            cp16(B + k * 72 + sc * 4, V + (size_t)(kb + k) * SDIM + s0 + sc * 4);
        }
        CP_COMMIT();
    };

    issue(0, 0);
    int buf = 0;

    for (int kb = 0; kb < CDIM; kb += BK) {
        const bool more = (kb + BK < CDIM);
        if (more) issue(buf ^ 1, kb + BK);
        if (more) cp_wait<1>(); else cp_wait<0>();
        __syncthreads();

        float* A = smem + buf * STAGE;
        float* B = A + ATILE;

        #pragma unroll
        for (int kk = 0; kk < BK; kk += 8) {
            uint32_t ah[4][4], bh[4][2];
            #pragma unroll
            for (int mr = 0; mr < 4; mr++) {
                const int r0 = warpM * 64 + mr * 16;
                ah[mr][0] = tf32rn(A[(r0 + gid    ) * 36 + kk + tig    ]);
                ah[mr][1] = tf32rn(A[(r0 + 8 + gid) * 36 + kk + tig    ]);
                ah[mr][2] = tf32rn(A[(r0 + gid    ) * 36 + kk + tig + 4]);
                ah[mr][3] = tf32rn(A[(r0 + 8 + gid) * 36 + kk + tig + 4]);
            }
            #pragma unroll
            for (int nc = 0; nc < 4; nc++) {
                const int n0 = warpN * 32 + nc * 8;
                bh[nc][0] = tf32rn(B[(kk + tig    ) * 72 + n0 + gid]);
                bh[nc][1] = tf32rn(B[(kk + tig + 4) * 72 + n0 + gid]);
            }
            #pragma unroll
            for (int mr = 0; mr < 4; mr++)
                #pragma unroll
                for (int nc = 0; nc < 4; nc++)
                    mma_tf32(acc[mr][nc], ah[mr], bh[nc]);
        }
        __syncthreads();
        buf ^= 1;
    }

    const float av = *alpha;
    float* outB = out + (size_t)b * CDIM * SDIM;
    #pragma unroll
    for (int mr = 0; mr < 4; mr++) {
        const int r = warpM * 64 + mr * 16 + gid;      // 0..255
        #pragma unroll
        for (int nc = 0; nc < 4; nc++) {
            const int s = s0 + warpN * 32 + nc * 8 + tig * 2;
            const size_t i0 = (size_t)r * SDIM + s;
            const size_t i1 = i0 + (size_t)8 * SDIM;
            const float2 x0 = *(const float2*)(V + i0);
            const float2 x1 = *(const float2*)(V + i1);
            *(float2*)(outB + i0) = make_float2(fmaf(av, acc[mr][nc][0], x0.x),
                                                fmaf(av, acc[mr][nc][1], x0.y));
            *(float2*)(outB + i1) = make_float2(fmaf(av, acc[mr][nc][2], x1.x),
                                                fmaf(av, acc[mr][nc][3], x1.y));
        }
    }
}

extern "C" void kernel_launch(void* const* d_in, const int* in_sizes, int n_in,
                              void* d_out, int out_size) {
    const float* x     = (const float*)d_in[0];
    const float* alpha = (const float*)d_in[1];
    float* out = (float*)d_out;

    // One-time host objects (created on the first, non-captured, correctness
    // call; reused inside graph capture — no device memory involved).
    static cudaStream_t s2 = nullptr;
    static cudaEvent_t evFork = nullptr, evJoin = nullptr;
    if (!s2) {
        cudaStreamCreateWithFlags(&s2, cudaStreamNonBlocking);
        cudaEventCreateWithFlags(&evFork, cudaEventDisableTiming);
        cudaEventCreateWithFlags(&evJoin, cudaEventDisableTiming);
    }

    const int smem1 = 4 * 128 * 36 * 4;                    // 73728 B
    const int smem2 = 2 * (256 * 36 + 32 * 72) * 4;        // 92160 B
    static bool attrs_set = false;
    if (!attrs_set) {
        cudaFuncSetAttribute(gemm1_kernel, cudaFuncAttributeMaxDynamicSharedMemorySize, smem1);
        cudaFuncSetAttribute(gemm2_kernel, cudaFuncAttributeMaxDynamicSharedMemorySize, smem2);
        attrs_set = true;
    }

    // Fork: group B (batches 4..7) on s2 concurrently with group A on main.
    cudaEventRecord(evFork, 0);
    cudaStreamWaitEvent(s2, evFork, 0);

    // Group A on main stream: batches 0..3
    gemm1_kernel<<<dim3(G1_CTAS, HB), 256, smem1>>>(x, 0);
    softmax_kernel<<<HB * CDIM, 256>>>(0);
    gemm2_kernel<<<dim3(SDIM / 64, HB), 256, smem2>>>(x, alpha, out, 0);

    // Group B on s2: batches 4..7
    gemm1_kernel<<<dim3(G1_CTAS, HB), 256, smem1, s2>>>(x, HB);
    softmax_kernel<<<HB * CDIM, 256, 0, s2>>>(HB * CDIM);
    gemm2_kernel<<<dim3(SDIM / 64, HB), 256, smem2, s2>>>(x, alpha, out, HB);

    cudaEventRecord(evJoin, s2);
    cudaStreamWaitEvent(0, evJoin, 0);
}